// round 2
// baseline (speedup 1.0000x reference)
#include <cuda_runtime.h>
#include <stdint.h>

// ============================================================================
// HeteroscedasticSoftmax: out = mean_{s<100} softmax(logits + eps_s * exp(log_std))
// eps_s reproduces jax.random.normal(split(key(1),100)[s], [8,19,256,256])
// bit-exactly (threefry2x32 counter PRNG + XLA/Giles erfinv).
// Partitionable threefry, 32-bit draw = x0_out ^ x1_out (jax/_src/prng.py).
// ============================================================================

#define NSAMP 100
#define NCH   19
#define NB    8
#define HW    65536            // 256*256
#define TOTAL_ELEMS (NB * NCH * HW)   // 9961472
#define HALF_ELEMS  (TOTAL_ELEMS / 2)

// ---- RNG variant switches (flip if rel_err shows wrong stream) -------------
#define RNG_PARTITIONABLE 1
#define BITS_WORD 2   // 0: low word, 1: high word, 2: xor (jax partitionable 32-bit)

__device__ uint2 d_keys[NSAMP];

__device__ __forceinline__ uint2 threefry2x32(uint32_t k0, uint32_t k1,
                                              uint32_t x0, uint32_t x1) {
  uint32_t k2 = k0 ^ k1 ^ 0x1BD11BDAu;
  x0 += k0; x1 += k1;
#define TF_ROUND(r) { x0 += x1; x1 = __funnelshift_l(x1, x1, (r)); x1 ^= x0; }
  TF_ROUND(13) TF_ROUND(15) TF_ROUND(26) TF_ROUND(6)
  x0 += k1; x1 += k2 + 1u;
  TF_ROUND(17) TF_ROUND(29) TF_ROUND(16) TF_ROUND(24)
  x0 += k2; x1 += k0 + 2u;
  TF_ROUND(13) TF_ROUND(15) TF_ROUND(26) TF_ROUND(6)
  x0 += k0; x1 += k1 + 3u;
  TF_ROUND(17) TF_ROUND(29) TF_ROUND(16) TF_ROUND(24)
  x0 += k1; x1 += k2 + 4u;
  TF_ROUND(13) TF_ROUND(15) TF_ROUND(26) TF_ROUND(6)
  x0 += k2; x1 += k0 + 5u;
#undef TF_ROUND
  return make_uint2(x0, x1);
}

// Derive the 100 sample keys from jax.random.key(1) = (0, 1).
__global__ void hs_keys_kernel() {
#if RNG_PARTITIONABLE
  int s = threadIdx.x;
  if (s < NSAMP) {
    d_keys[s] = threefry2x32(0u, 1u, 0u, (uint32_t)s);
  }
#else
  __shared__ uint32_t outw[2 * NSAMP];
  int s = threadIdx.x;
  if (s < NSAMP) {
    uint2 o = threefry2x32(0u, 1u, (uint32_t)s, (uint32_t)(s + NSAMP));
    outw[s] = o.x;
    outw[NSAMP + s] = o.y;
  }
  __syncthreads();
  if (s < NSAMP) d_keys[s] = make_uint2(outw[2 * s], outw[2 * s + 1]);
#endif
}

// XLA ErfInv32 (Giles single-precision approximation).
__device__ __forceinline__ float erfinv_xla(float x) {
  float w = -__logf(fmaf(-x, x, 1.0f));   // -log1p(-x*x)
  float p;
  if (w < 5.0f) {
    w = w - 2.5f;
    p = 2.81022636e-08f;
    p = fmaf(p, w, 3.43273939e-07f);
    p = fmaf(p, w, -3.5233877e-06f);
    p = fmaf(p, w, -4.39150654e-06f);
    p = fmaf(p, w, 0.00021858087f);
    p = fmaf(p, w, -0.00125372503f);
    p = fmaf(p, w, -0.00417768164f);
    p = fmaf(p, w, 0.246640727f);
    p = fmaf(p, w, 1.50140941f);
  } else {
    w = sqrtf(w) - 3.0f;
    p = -0.000200214257f;
    p = fmaf(p, w, 0.000100950558f);
    p = fmaf(p, w, 0.00134934322f);
    p = fmaf(p, w, -0.00367342844f);
    p = fmaf(p, w, 0.00573950773f);
    p = fmaf(p, w, -0.0076224613f);
    p = fmaf(p, w, 0.00943887047f);
    p = fmaf(p, w, 1.00167406f);
    p = fmaf(p, w, 2.83297682f);
  }
  return p * x;
}

// bits -> eps: jax uniform(lo, 1.0) then sqrt(2)*erfinv(u)
#define JAX_LO (-0.99999994f)          // nextafter(-1, 0) in fp32
#define SQRT2_F 1.41421356f            // fp32(np.sqrt(2))

__device__ __forceinline__ float bits_to_eps(uint32_t bits) {
  float g = __uint_as_float((bits >> 9) | 0x3F800000u);  // [1, 2)
  float f = g - 1.0f;                                    // exact
  float u = __fadd_rn(__fmul_rn(f, 2.0f), JAX_LO);       // (hi-lo) rounds to 2.0f
  u = fmaxf(JAX_LO, u);
  return SQRT2_F * erfinv_xla(u);
}

__global__ __launch_bounds__(128)
void hs_main_kernel(const float* __restrict__ in, float* __restrict__ out) {
  __shared__ uint2 sk[NSAMP];
  int t = threadIdx.x;
  if (t < NSAMP) sk[t] = d_keys[t];
  __syncthreads();

  unsigned T = blockIdx.x * 128u + (unsigned)t;   // 0 .. 524287
  if (T >= (unsigned)(NB * HW)) return;
  unsigned b = T >> 16;
  unsigned hw = T & 0xFFFFu;

  const float* pin = in + (size_t)b * (2 * NCH) * HW + hw;
  float lg[NCH], sd[NCH], acc[NCH];
#pragma unroll
  for (int c = 0; c < NCH; c++) {
    lg[c] = pin[(size_t)c * HW];
    sd[c] = __expf(pin[(size_t)(NCH + c) * HW]);
    acc[c] = 0.0f;
  }

  const uint32_t ctrBase = b * (NCH * HW) + hw;   // flat idx of (b, 0, hw)

#pragma unroll 1
  for (int s = 0; s < NSAMP; s++) {
    const uint2 k = sk[s];
    float z[NCH];
#pragma unroll
    for (int c = 0; c < NCH; c++) {
      uint32_t idx = ctrBase + ((uint32_t)c << 16);
      uint32_t bits;
#if RNG_PARTITIONABLE
      uint2 o = threefry2x32(k.x, k.y, 0u, idx);
#if BITS_WORD == 0
      bits = o.y;
#elif BITS_WORD == 1
      bits = o.x;
#else
      bits = o.x ^ o.y;
#endif
#else
      if (idx < (uint32_t)HALF_ELEMS) {
        uint2 o = threefry2x32(k.x, k.y, idx, idx + (uint32_t)HALF_ELEMS);
        bits = o.x;
      } else {
        uint2 o = threefry2x32(k.x, k.y, idx - (uint32_t)HALF_ELEMS, idx);
        bits = o.y;
      }
#endif
      float eps = bits_to_eps(bits);
      z[c] = fmaf(eps, sd[c], lg[c]);
    }
    // softmax over channels (max-subtracted, like jax.nn.softmax)
    float m = z[0];
#pragma unroll
    for (int c = 1; c < NCH; c++) m = fmaxf(m, z[c]);
    float sum = 0.0f;
#pragma unroll
    for (int c = 0; c < NCH; c++) {
      float e = __expf(z[c] - m);
      z[c] = e;
      sum += e;
    }
    float inv = __fdividef(1.0f, sum);
#pragma unroll
    for (int c = 0; c < NCH; c++) acc[c] = fmaf(z[c], inv, acc[c]);
  }

  float* pout = out + (size_t)b * NCH * HW + hw;
#pragma unroll
  for (int c = 0; c < NCH; c++) pout[(size_t)c * HW] = acc[c] * 0.01f;
}

extern "C" void kernel_launch(void* const* d_in, const int* in_sizes, int n_in,
                              void* d_out, int out_size) {
  (void)in_sizes; (void)n_in; (void)out_size;
  const float* in = (const float*)d_in[0];
  float* out = (float*)d_out;

  hs_keys_kernel<<<1, 128>>>();
  // 8 batches * 65536 spatial = 524288 threads, one per (b, h, w)
  hs_main_kernel<<<4096, 128>>>(in, out);
}

// round 3
// speedup vs baseline: 1.6004x; 1.6004x over previous
#include <cuda_runtime.h>
#include <stdint.h>

// ============================================================================
// HeteroscedasticSoftmax: out = mean_{s<100} softmax(logits + eps_s * exp(log_std))
// eps_s reproduces jax.random.normal(split(key(1),100)[s], [8,19,256,256])
// bit-exactly (partitionable threefry2x32; 32-bit draw = x0_out ^ x1_out;
// XLA/Giles erfinv).
//
// R3: alu-pipe was binding (72.8% vs fma 26.9%). Round-adds forced onto IMAD
// (fma pipe) via opaque multiplier; reg cap 85 for 6 blocks/SM; keys fused.
// ============================================================================

#define NSAMP 100
#define NCH   19
#define NB    8
#define HW    65536            // 256*256

// Opaque 1 — loaded from memory so ptxas cannot const-fold the IMADs below
// back into IADD3 (we want them on the fma pipe to balance alu/fma).
__device__ uint32_t d_one = 1u;

__device__ __forceinline__ uint32_t imad1(uint32_t a, uint32_t one, uint32_t b) {
  uint32_t r;
  asm("mad.lo.u32 %0, %1, %2, %3;" : "=r"(r) : "r"(a), "r"(one), "r"(b));
  return r;
}

// Threefry2x32 with round-adds on the fma pipe (IMAD via opaque `one`).
__device__ __forceinline__ uint2 threefry2x32_bal(uint32_t k0, uint32_t k1,
                                                  uint32_t x0, uint32_t x1,
                                                  uint32_t one) {
  uint32_t k2 = k0 ^ k1 ^ 0x1BD11BDAu;
  x0 += k0; x1 += k1;
#define TF_ROUND(r) { x0 = imad1(x0, one, x1); x1 = __funnelshift_l(x1, x1, (r)); x1 ^= x0; }
  TF_ROUND(13) TF_ROUND(15) TF_ROUND(26) TF_ROUND(6)
  x0 += k1; x1 += k2 + 1u;
  TF_ROUND(17) TF_ROUND(29) TF_ROUND(16) TF_ROUND(24)
  x0 += k2; x1 += k0 + 2u;
  TF_ROUND(13) TF_ROUND(15) TF_ROUND(26) TF_ROUND(6)
  x0 += k0; x1 += k1 + 3u;
  TF_ROUND(17) TF_ROUND(29) TF_ROUND(16) TF_ROUND(24)
  x0 += k1; x1 += k2 + 4u;
  TF_ROUND(13) TF_ROUND(15) TF_ROUND(26) TF_ROUND(6)
  x0 += k2; x1 += k0 + 5u;
#undef TF_ROUND
  return make_uint2(x0, x1);
}

// Plain version (key derivation; not perf-critical).
__device__ __forceinline__ uint2 threefry2x32(uint32_t k0, uint32_t k1,
                                              uint32_t x0, uint32_t x1) {
  uint32_t k2 = k0 ^ k1 ^ 0x1BD11BDAu;
  x0 += k0; x1 += k1;
#define TF_ROUND(r) { x0 += x1; x1 = __funnelshift_l(x1, x1, (r)); x1 ^= x0; }
  TF_ROUND(13) TF_ROUND(15) TF_ROUND(26) TF_ROUND(6)
  x0 += k1; x1 += k2 + 1u;
  TF_ROUND(17) TF_ROUND(29) TF_ROUND(16) TF_ROUND(24)
  x0 += k2; x1 += k0 + 2u;
  TF_ROUND(13) TF_ROUND(15) TF_ROUND(26) TF_ROUND(6)
  x0 += k0; x1 += k1 + 3u;
  TF_ROUND(17) TF_ROUND(29) TF_ROUND(16) TF_ROUND(24)
  x0 += k1; x1 += k2 + 4u;
  TF_ROUND(13) TF_ROUND(15) TF_ROUND(26) TF_ROUND(6)
  x0 += k2; x1 += k0 + 5u;
#undef TF_ROUND
  return make_uint2(x0, x1);
}

// XLA ErfInv32 (Giles single-precision approximation).
__device__ __forceinline__ float erfinv_xla(float x) {
  float w = -__logf(fmaf(-x, x, 1.0f));   // -log1p(-x*x)
  float p;
  if (w < 5.0f) {
    w = w - 2.5f;
    p = 2.81022636e-08f;
    p = fmaf(p, w, 3.43273939e-07f);
    p = fmaf(p, w, -3.5233877e-06f);
    p = fmaf(p, w, -4.39150654e-06f);
    p = fmaf(p, w, 0.00021858087f);
    p = fmaf(p, w, -0.00125372503f);
    p = fmaf(p, w, -0.00417768164f);
    p = fmaf(p, w, 0.246640727f);
    p = fmaf(p, w, 1.50140941f);
  } else {
    w = sqrtf(w) - 3.0f;
    p = -0.000200214257f;
    p = fmaf(p, w, 0.000100950558f);
    p = fmaf(p, w, 0.00134934322f);
    p = fmaf(p, w, -0.00367342844f);
    p = fmaf(p, w, 0.00573950773f);
    p = fmaf(p, w, -0.0076224613f);
    p = fmaf(p, w, 0.00943887047f);
    p = fmaf(p, w, 1.00167406f);
    p = fmaf(p, w, 2.83297682f);
  }
  return p * x;
}

// bits -> eps: jax uniform(lo, 1.0) (separate mul/add rounding like XLA),
// then sqrt(2)*erfinv(u)
#define JAX_LO (-0.99999994f)          // nextafter(-1, 0) in fp32
#define SQRT2_F 1.41421356f            // fp32(np.sqrt(2))

__device__ __forceinline__ float bits_to_eps(uint32_t bits) {
  float g = __uint_as_float((bits >> 9) | 0x3F800000u);  // [1, 2)
  float f = g - 1.0f;                                    // exact
  float u = __fadd_rn(__fmul_rn(f, 2.0f), JAX_LO);       // XLA: mul, then add
  u = fmaxf(JAX_LO, u);
  return SQRT2_F * erfinv_xla(u);
}

__global__ __launch_bounds__(128, 6)
void hs_main_kernel(const float* __restrict__ in, float* __restrict__ out) {
  __shared__ uint2 sk[NSAMP];
  int t = threadIdx.x;
  // Derive the 100 sample keys from jax.random.key(1) = (0, 1) in-block
  // (foldlike split: keys[s] = threefry(key, (0, s))).
  if (t < NSAMP) sk[t] = threefry2x32(0u, 1u, 0u, (uint32_t)t);

  const uint32_t one = d_one;   // opaque 1 for the IMAD balancing trick
  __syncthreads();

  unsigned T = blockIdx.x * 128u + (unsigned)t;   // 0 .. 524287
  unsigned b = T >> 16;
  unsigned hw = T & 0xFFFFu;

  const float* pin = in + (size_t)b * (2 * NCH) * HW + hw;
  float lg[NCH], sd[NCH], acc[NCH];
#pragma unroll
  for (int c = 0; c < NCH; c++) {
    lg[c] = pin[(size_t)c * HW];
    sd[c] = __expf(pin[(size_t)(NCH + c) * HW]);
    acc[c] = 0.0f;
  }

  const uint32_t ctrBase = b * (NCH * HW) + hw;   // flat idx of (b, 0, hw)

#pragma unroll 1
  for (int s = 0; s < NSAMP; s++) {
    const uint2 k = sk[s];
    const uint32_t baseK1 = ctrBase + k.y;  // fold k1 into the counter init
    float z[NCH];
#pragma unroll
    for (int c = 0; c < NCH; c++) {
      // counter = (0, ctrBase + c*HW); x1 init add folded: baseK1 + (c<<16)
      uint2 o = threefry2x32_bal(k.x, k.y, 0u,
                                 baseK1 + ((uint32_t)c << 16) - k.y, one);
      uint32_t bits = o.x ^ o.y;     // jax partitionable 32-bit draw
      float eps = bits_to_eps(bits);
      z[c] = fmaf(eps, sd[c], lg[c]);
    }
    // softmax over channels (max-subtracted, like jax.nn.softmax)
    float m = z[0];
#pragma unroll
    for (int c = 1; c < NCH; c++) m = fmaxf(m, z[c]);
    float sum = 0.0f;
#pragma unroll
    for (int c = 0; c < NCH; c++) {
      float e = __expf(z[c] - m);
      z[c] = e;
      sum += e;
    }
    float inv = __fdividef(1.0f, sum);
#pragma unroll
    for (int c = 0; c < NCH; c++) acc[c] = fmaf(z[c], inv, acc[c]);
  }

  float* pout = out + (size_t)b * NCH * HW + hw;
#pragma unroll
  for (int c = 0; c < NCH; c++) pout[(size_t)c * HW] = acc[c] * 0.01f;
}

extern "C" void kernel_launch(void* const* d_in, const int* in_sizes, int n_in,
                              void* d_out, int out_size) {
  (void)in_sizes; (void)n_in; (void)out_size;
  const float* in = (const float*)d_in[0];
  float* out = (float*)d_out;

  // 8 batches * 65536 spatial = 524288 threads, one per (b, h, w)
  hs_main_kernel<<<4096, 128>>>(in, out);
}

// round 4
// speedup vs baseline: 1.6897x; 1.0558x over previous
#include <cuda_runtime.h>
#include <stdint.h>

// ============================================================================
// HeteroscedasticSoftmax: out = mean_{s<100} softmax(logits + eps_s * exp(log_std))
// eps_s reproduces jax.random.normal(split(key(1),100)[s], [8,19,256,256])
// bit-exactly (partitionable threefry2x32; 32-bit draw = x0_out ^ x1_out;
// XLA/Giles erfinv).
//
// R4: balance alu/fma pipes. Round adds AND injection adds on IMAD (fma pipe)
// via opaque multiplier; bits-prep via IMAD.HI; clamp removed (proven no-op);
// u via single FMA (bit-identical).
// ============================================================================

#define NSAMP 100
#define NCH   19
#define NB    8
#define HW    65536            // 256*256

// Opaque 1 — loaded from memory so ptxas cannot const-fold the IMADs below
// back into IADD3 (we want them on the fma pipe to balance alu/fma).
__device__ uint32_t d_one = 1u;

__device__ __forceinline__ uint32_t imad1(uint32_t a, uint32_t one, uint32_t b) {
  uint32_t r;
  asm("mad.lo.u32 %0, %1, %2, %3;" : "=r"(r) : "r"(a), "r"(one), "r"(b));
  return r;
}

// (bits >> 9) + 0x3F800000 on the fma pipe (IMAD.HI). Equals the OR form
// because the two fields are bit-disjoint (bits>>9 < 2^23).
__device__ __forceinline__ uint32_t mantissa_to_one_two(uint32_t bits) {
  uint32_t r;
  asm("mad.hi.u32 %0, %1, %2, %3;" : "=r"(r)
      : "r"(bits), "n"(1u << 23), "n"(0x3F800000u));
  return r;
}

// Threefry2x32, 20 rounds + key injections, integer adds on the fma pipe.
// Takes pre-injected state (x0 = k0, x1 = ctr + k1 done by caller).
__device__ __forceinline__ uint32_t threefry2x32_x(
    uint32_t x0, uint32_t x1,
    uint32_t j1a, uint32_t j1b,   // k1,   k2+1
    uint32_t j2a, uint32_t j2b,   // k2,   k0+2
    uint32_t j3a, uint32_t j3b,   // k0,   k1+3
    uint32_t j4a, uint32_t j4b,   // k1,   k2+4
    uint32_t j5a, uint32_t j5b,   // k2,   k0+5
    uint32_t one) {
#define TF_ROUND(r) { x0 = imad1(x0, one, x1); x1 = __funnelshift_l(x1, x1, (r)); x1 ^= x0; }
#define TF_INJ(a, b) { x0 = imad1(x0, one, (a)); x1 = imad1(x1, one, (b)); }
  TF_ROUND(13) TF_ROUND(15) TF_ROUND(26) TF_ROUND(6)
  TF_INJ(j1a, j1b)
  TF_ROUND(17) TF_ROUND(29) TF_ROUND(16) TF_ROUND(24)
  TF_INJ(j2a, j2b)
  TF_ROUND(13) TF_ROUND(15) TF_ROUND(26) TF_ROUND(6)
  TF_INJ(j3a, j3b)
  TF_ROUND(17) TF_ROUND(29) TF_ROUND(16) TF_ROUND(24)
  TF_INJ(j4a, j4b)
  TF_ROUND(13) TF_ROUND(15) TF_ROUND(26) TF_ROUND(6)
  TF_INJ(j5a, j5b)
#undef TF_ROUND
#undef TF_INJ
  return x0 ^ x1;   // jax partitionable 32-bit draw
}

// Plain version (key derivation only; once per block).
__device__ __forceinline__ uint2 threefry2x32(uint32_t k0, uint32_t k1,
                                              uint32_t x0, uint32_t x1) {
  uint32_t k2 = k0 ^ k1 ^ 0x1BD11BDAu;
  x0 += k0; x1 += k1;
#define TF_ROUND(r) { x0 += x1; x1 = __funnelshift_l(x1, x1, (r)); x1 ^= x0; }
  TF_ROUND(13) TF_ROUND(15) TF_ROUND(26) TF_ROUND(6)
  x0 += k1; x1 += k2 + 1u;
  TF_ROUND(17) TF_ROUND(29) TF_ROUND(16) TF_ROUND(24)
  x0 += k2; x1 += k0 + 2u;
  TF_ROUND(13) TF_ROUND(15) TF_ROUND(26) TF_ROUND(6)
  x0 += k0; x1 += k1 + 3u;
  TF_ROUND(17) TF_ROUND(29) TF_ROUND(16) TF_ROUND(24)
  x0 += k1; x1 += k2 + 4u;
  TF_ROUND(13) TF_ROUND(15) TF_ROUND(26) TF_ROUND(6)
  x0 += k2; x1 += k0 + 5u;
#undef TF_ROUND
  return make_uint2(x0, x1);
}

// XLA ErfInv32 (Giles single-precision approximation).
__device__ __forceinline__ float erfinv_xla(float x) {
  float w = -__logf(fmaf(-x, x, 1.0f));   // -log1p(-x*x)
  float p;
  if (w < 5.0f) {
    w = w - 2.5f;
    p = 2.81022636e-08f;
    p = fmaf(p, w, 3.43273939e-07f);
    p = fmaf(p, w, -3.5233877e-06f);
    p = fmaf(p, w, -4.39150654e-06f);
    p = fmaf(p, w, 0.00021858087f);
    p = fmaf(p, w, -0.00125372503f);
    p = fmaf(p, w, -0.00417768164f);
    p = fmaf(p, w, 0.246640727f);
    p = fmaf(p, w, 1.50140941f);
  } else {
    w = sqrtf(w) - 3.0f;
    p = -0.000200214257f;
    p = fmaf(p, w, 0.000100950558f);
    p = fmaf(p, w, 0.00134934322f);
    p = fmaf(p, w, -0.00367342844f);
    p = fmaf(p, w, 0.00573950773f);
    p = fmaf(p, w, -0.0076224613f);
    p = fmaf(p, w, 0.00943887047f);
    p = fmaf(p, w, 1.00167406f);
    p = fmaf(p, w, 2.83297682f);
  }
  return p * x;
}

#define JAX_LO (-0.99999994f)          // nextafter(-1, 0) in fp32
#define SQRT2_F 1.41421356f            // fp32(np.sqrt(2))

__device__ __forceinline__ float bits_to_eps(uint32_t bits) {
  float g = __uint_as_float(mantissa_to_one_two(bits));  // [1, 2)
  float f = g - 1.0f;                                    // exact
  // u = rn(2f + lo): 2f exact, so single FMA == XLA's mul-then-add.
  // Clamp max(lo, u) is a proven no-op (f >= 0 -> u >= lo under rn).
  float u = fmaf(f, 2.0f, JAX_LO);
  return SQRT2_F * erfinv_xla(u);
}

__global__ __launch_bounds__(128, 6)
void hs_main_kernel(const float* __restrict__ in, float* __restrict__ out) {
  __shared__ uint2 sk[NSAMP];
  int t = threadIdx.x;
  // Derive the 100 sample keys from jax.random.key(1) = (0, 1) in-block
  // (foldlike split: keys[s] = threefry(key, (0, s))).
  if (t < NSAMP) sk[t] = threefry2x32(0u, 1u, 0u, (uint32_t)t);

  const uint32_t one = d_one;   // opaque 1 for the IMAD balancing trick
  __syncthreads();

  unsigned T = blockIdx.x * 128u + (unsigned)t;   // 0 .. 524287
  unsigned b = T >> 16;
  unsigned hw = T & 0xFFFFu;

  const float* pin = in + (size_t)b * (2 * NCH) * HW + hw;
  float lg[NCH], sd[NCH], acc[NCH];
#pragma unroll
  for (int c = 0; c < NCH; c++) {
    lg[c] = pin[(size_t)c * HW];
    sd[c] = __expf(pin[(size_t)(NCH + c) * HW]);
    acc[c] = 0.0f;
  }

  const uint32_t ctrBase = b * (NCH * HW) + hw;   // flat idx of (b, 0, hw)

#pragma unroll 1
  for (int s = 0; s < NSAMP; s++) {
    const uint2 k = sk[s];
    const uint32_t k0 = k.x, k1 = k.y;
    const uint32_t k2 = k0 ^ k1 ^ 0x1BD11BDAu;
    // Key-schedule injection values (hoisted per sample, reused for 19 draws).
    const uint32_t j1b = k2 + 1u, j2b = k0 + 2u, j3b = k1 + 3u,
                   j4b = k2 + 4u, j5b = k0 + 5u;
    const uint32_t x1base = ctrBase + k1;   // counter lo + initial k1 inject
    float z[NCH];
#pragma unroll
    for (int c = 0; c < NCH; c++) {
      // counter = (0, ctrBase + c*HW); x0 init = 0 + k0 = k0.
      uint32_t bits = threefry2x32_x(k0, x1base + ((uint32_t)c << 16),
                                     k1, j1b, k2, j2b, k0, j3b,
                                     k1, j4b, k2, j5b, one);
      float eps = bits_to_eps(bits);
      z[c] = fmaf(eps, sd[c], lg[c]);
    }
    // softmax over channels (max-subtracted, like jax.nn.softmax)
    float m = z[0];
#pragma unroll
    for (int c = 1; c < NCH; c++) m = fmaxf(m, z[c]);
    float sum = 0.0f;
#pragma unroll
    for (int c = 0; c < NCH; c++) {
      float e = __expf(z[c] - m);
      z[c] = e;
      sum += e;
    }
    float inv = __fdividef(0.01f, sum);  // fold the 1/NSAMP mean factor in
#pragma unroll
    for (int c = 0; c < NCH; c++) acc[c] = fmaf(z[c], inv, acc[c]);
  }

  float* pout = out + (size_t)b * NCH * HW + hw;
#pragma unroll
  for (int c = 0; c < NCH; c++) pout[(size_t)c * HW] = acc[c];
}

extern "C" void kernel_launch(void* const* d_in, const int* in_sizes, int n_in,
                              void* d_out, int out_size) {
  (void)in_sizes; (void)n_in; (void)out_size;
  const float* in = (const float*)d_in[0];
  float* out = (float*)d_out;

  // 8 batches * 65536 spatial = 524288 threads, one per (b, h, w)
  hs_main_kernel<<<4096, 128>>>(in, out);
}

// round 5
// speedup vs baseline: 1.8518x; 1.0959x over previous
#include <cuda_runtime.h>
#include <stdint.h>

// ============================================================================
// HeteroscedasticSoftmax: out = mean_{s<100} softmax(logits + eps_s * exp(log_std))
// eps_s reproduces jax.random.normal(split(key(1),100)[s], [8,19,256,256])
// bit-exactly (partitionable threefry2x32; 32-bit draw = x0_out ^ x1_out;
// XLA/Giles erfinv).
//
// R5: occupancy push. lg/sd prescaled into smem float2 (frees ~38 regs,
// 8 blocks/SM); log2-domain softmax (raw EX2, no per-exp FMUL, sqrt2 folded
// into sd); erfinv -ln2 folded into branch-1 offset; counter-init on IMAD.
// ============================================================================

#define NSAMP 100
#define NCH   19
#define NB    8
#define HW    65536            // 256*256

// Opaque 1 — keeps integer adds as IMAD (fma pipe) instead of IADD3 (alu).
__device__ uint32_t d_one = 1u;

__device__ __forceinline__ uint32_t imad1(uint32_t a, uint32_t one, uint32_t b) {
  uint32_t r;
  asm("mad.lo.u32 %0, %1, %2, %3;" : "=r"(r) : "r"(a), "r"(one), "r"(b));
  return r;
}

// (bits >> 9) + 0x3F800000 on the fma pipe (IMAD.HI); equals OR (disjoint bits).
__device__ __forceinline__ uint32_t mantissa_to_one_two(uint32_t bits) {
  uint32_t r;
  asm("mad.hi.u32 %0, %1, %2, %3;" : "=r"(r)
      : "r"(bits), "n"(1u << 23), "n"(0x3F800000u));
  return r;
}

__device__ __forceinline__ float ex2_approx(float x) {
  float r; asm("ex2.approx.f32 %0, %1;" : "=f"(r) : "f"(x)); return r;
}
__device__ __forceinline__ float lg2_approx(float x) {
  float r; asm("lg2.approx.f32 %0, %1;" : "=f"(r) : "f"(x)); return r;
}

// Threefry2x32 (20 rounds), integer adds on the fma pipe. Caller pre-injects
// (x0 = k0, x1 = ctr + k1). Returns x0^x1 (jax partitionable 32-bit draw).
__device__ __forceinline__ uint32_t threefry2x32_x(
    uint32_t x0, uint32_t x1,
    uint32_t j1a, uint32_t j1b, uint32_t j2a, uint32_t j2b,
    uint32_t j3a, uint32_t j3b, uint32_t j4a, uint32_t j4b,
    uint32_t j5a, uint32_t j5b, uint32_t one) {
#define TF_ROUND(r) { x0 = imad1(x0, one, x1); x1 = __funnelshift_l(x1, x1, (r)); x1 ^= x0; }
#define TF_INJ(a, b) { x0 = imad1(x0, one, (a)); x1 = imad1(x1, one, (b)); }
  TF_ROUND(13) TF_ROUND(15) TF_ROUND(26) TF_ROUND(6)
  TF_INJ(j1a, j1b)
  TF_ROUND(17) TF_ROUND(29) TF_ROUND(16) TF_ROUND(24)
  TF_INJ(j2a, j2b)
  TF_ROUND(13) TF_ROUND(15) TF_ROUND(26) TF_ROUND(6)
  TF_INJ(j3a, j3b)
  TF_ROUND(17) TF_ROUND(29) TF_ROUND(16) TF_ROUND(24)
  TF_INJ(j4a, j4b)
  TF_ROUND(13) TF_ROUND(15) TF_ROUND(26) TF_ROUND(6)
  TF_INJ(j5a, j5b)
#undef TF_ROUND
#undef TF_INJ
  return x0 ^ x1;
}

// Plain version (key derivation only; once per block).
__device__ __forceinline__ uint2 threefry2x32(uint32_t k0, uint32_t k1,
                                              uint32_t x0, uint32_t x1) {
  uint32_t k2 = k0 ^ k1 ^ 0x1BD11BDAu;
  x0 += k0; x1 += k1;
#define TF_ROUND(r) { x0 += x1; x1 = __funnelshift_l(x1, x1, (r)); x1 ^= x0; }
  TF_ROUND(13) TF_ROUND(15) TF_ROUND(26) TF_ROUND(6)
  x0 += k1; x1 += k2 + 1u;
  TF_ROUND(17) TF_ROUND(29) TF_ROUND(16) TF_ROUND(24)
  x0 += k2; x1 += k0 + 2u;
  TF_ROUND(13) TF_ROUND(15) TF_ROUND(26) TF_ROUND(6)
  x0 += k0; x1 += k1 + 3u;
  TF_ROUND(17) TF_ROUND(29) TF_ROUND(16) TF_ROUND(24)
  x0 += k1; x1 += k2 + 4u;
  TF_ROUND(13) TF_ROUND(15) TF_ROUND(26) TF_ROUND(6)
  x0 += k2; x1 += k0 + 5u;
#undef TF_ROUND
  return make_uint2(x0, x1);
}

#define JAX_LO (-0.99999994f)          // nextafter(-1, 0) in fp32
#define NEG_LN2 (-0.69314718f)
// w = -ln2*lg2(y); branch "w < 5"  <=>  lg2(y) > 5/-ln2
#define LG2_BRANCH (-7.21347520f)

// XLA ErfInv32 (Giles) WITHOUT the final sqrt2 (folded into sd prescale).
// Returns erfinv(x) given x.
__device__ __forceinline__ float erfinv_raw(float x) {
  float y = fmaf(-x, x, 1.0f);          // 1 - x^2
  float wl = lg2_approx(y);             // lg2(y); w = -ln2 * wl
  float p;
  if (wl > LG2_BRANCH) {                // common path (w < 5), ~99.66%
    float w = fmaf(wl, NEG_LN2, -2.5f); // w - 2.5 fused
    p = 2.81022636e-08f;
    p = fmaf(p, w, 3.43273939e-07f);
    p = fmaf(p, w, -3.5233877e-06f);
    p = fmaf(p, w, -4.39150654e-06f);
    p = fmaf(p, w, 0.00021858087f);
    p = fmaf(p, w, -0.00125372503f);
    p = fmaf(p, w, -0.00417768164f);
    p = fmaf(p, w, 0.246640727f);
    p = fmaf(p, w, 1.50140941f);
  } else {
    float w = sqrtf(wl * NEG_LN2) - 3.0f;
    p = -0.000200214257f;
    p = fmaf(p, w, 0.000100950558f);
    p = fmaf(p, w, 0.00134934322f);
    p = fmaf(p, w, -0.00367342844f);
    p = fmaf(p, w, 0.00573950773f);
    p = fmaf(p, w, -0.0076224613f);
    p = fmaf(p, w, 0.00943887047f);
    p = fmaf(p, w, 1.00167406f);
    p = fmaf(p, w, 2.83297682f);
  }
  return p * x;
}

__device__ __forceinline__ float bits_to_eps_raw(uint32_t bits) {
  float g = __uint_as_float(mantissa_to_one_two(bits));  // [1, 2)
  float f = g - 1.0f;                                    // exact
  float u = fmaf(f, 2.0f, JAX_LO);   // == XLA mul+add; clamp is a proven no-op
  return erfinv_raw(u);              // sqrt2 folded into sd prescale
}

#define LOG2E 1.44269504f
#define SQRT2_LOG2E 2.04009342f       // sqrt(2) * log2(e)

__global__ __launch_bounds__(128, 8)
void hs_main_kernel(const float* __restrict__ in, float* __restrict__ out) {
  __shared__ uint2 sk[NSAMP];
  __shared__ float2 lgsd[NCH][128];   // (.x = logits*log2e, .y = std*sqrt2*log2e)
  int t = threadIdx.x;
  // Derive the 100 sample keys from jax.random.key(1) = (0, 1) in-block.
  if (t < NSAMP) sk[t] = threefry2x32(0u, 1u, 0u, (uint32_t)t);

  const uint32_t one = d_one;

  unsigned T = blockIdx.x * 128u + (unsigned)t;   // 0 .. 524287
  unsigned b = T >> 16;
  unsigned hw = T & 0xFFFFu;

  const float* pin = in + (size_t)b * (2 * NCH) * HW + hw;
#pragma unroll
  for (int c = 0; c < NCH; c++) {
    float l = pin[(size_t)c * HW];
    float s = __expf(pin[(size_t)(NCH + c) * HW]);
    lgsd[c][t] = make_float2(l * LOG2E, s * SQRT2_LOG2E);
  }
  __syncthreads();

  float acc[NCH];
#pragma unroll
  for (int c = 0; c < NCH; c++) acc[c] = 0.0f;

  const uint32_t ctrBase = b * (NCH * HW) + hw;   // flat idx of (b, 0, hw)

#pragma unroll 1
  for (int s = 0; s < NSAMP; s++) {
    const uint2 k = sk[s];
    const uint32_t k0 = k.x, k1 = k.y;
    const uint32_t k2 = k0 ^ k1 ^ 0x1BD11BDAu;
    const uint32_t j1b = k2 + 1u, j2b = k0 + 2u, j3b = k1 + 3u,
                   j4b = k2 + 4u, j5b = k0 + 5u;
    const uint32_t x1base = ctrBase + k1;   // counter lo + initial k1 inject
    float z[NCH];
#pragma unroll
    for (int c = 0; c < NCH; c++) {
      // counter = (0, ctrBase + c*HW); x0 init = 0 + k0.
      uint32_t x1 = imad1(x1base, one, (uint32_t)c << 16);
      uint32_t bits = threefry2x32_x(k0, x1,
                                     k1, j1b, k2, j2b, k0, j3b,
                                     k1, j4b, k2, j5b, one);
      float er = bits_to_eps_raw(bits);
      float2 ls = lgsd[c][t];
      z[c] = fmaf(er, ls.y, ls.x);       // log2-domain logits+eps*std
    }
    // softmax over channels in log2 domain
    float m = z[0];
#pragma unroll
    for (int c = 1; c < NCH; c++) m = fmaxf(m, z[c]);
    float sum = 0.0f;
#pragma unroll
    for (int c = 0; c < NCH; c++) {
      float e = ex2_approx(z[c] - m);
      z[c] = e;
      sum += e;
    }
    float inv = __fdividef(0.01f, sum);  // 1/NSAMP folded in
#pragma unroll
    for (int c = 0; c < NCH; c++) acc[c] = fmaf(z[c], inv, acc[c]);
  }

  float* pout = out + (size_t)b * NCH * HW + hw;
#pragma unroll
  for (int c = 0; c < NCH; c++) pout[(size_t)c * HW] = acc[c];
}

extern "C" void kernel_launch(void* const* d_in, const int* in_sizes, int n_in,
                              void* d_out, int out_size) {
  (void)in_sizes; (void)n_in; (void)out_size;
  const float* in = (const float*)d_in[0];
  float* out = (float*)d_out;

  // 8 batches * 65536 spatial = 524288 threads, one per (b, h, w)
  hs_main_kernel<<<4096, 128>>>(in, out);
}